// round 17
// baseline (speedup 1.0000x reference)
#include <cuda_runtime.h>
#include <math.h>
#include <float.h>

#define B_    2
#define S_    2048
#define DIM_  2048
#define H_    16
#define KVH_  4
#define HD_   128
#define G_    4
#define M_    (B_*S_)          // 4096 rows total
#define QD_   (H_*HD_)         // 2048
#define KD_   (KVH_*HD_)       // 512

// Scratch (device globals -- no allocation)
__device__ float g_q[(size_t)M_*QD_];     // [b,s,h,hd]
__device__ float g_k[(size_t)M_*KD_];     // [b,s,kvh,hd]
__device__ float g_v[(size_t)M_*KD_];
__device__ float g_attn[(size_t)M_*QD_];  // [b,s,h,hd]

// ---------------------------------------------------------------------------
// helpers
// ---------------------------------------------------------------------------
__device__ __forceinline__ unsigned pk2(float lo_elem, float hi_elem) {
    unsigned d;
    asm("cvt.rn.bf16x2.f32 %0, %1, %2;" : "=r"(d) : "f"(hi_elem), "f"(lo_elem));
    return d;
}
__device__ __forceinline__ float blo(unsigned u) { return __uint_as_float(u << 16); }
__device__ __forceinline__ float bhi(unsigned u) { return __uint_as_float(u & 0xffff0000u); }

#define MMA_BF16(d, a0, a1, a2, a3, b0, b1) \
    asm volatile("mma.sync.aligned.m16n8k16.row.col.f32.bf16.bf16.f32 " \
                 "{%0,%1,%2,%3},{%4,%5,%6,%7},{%8,%9},{%0,%1,%2,%3};" \
                 : "+f"(d[0]), "+f"(d[1]), "+f"(d[2]), "+f"(d[3]) \
                 : "r"(a0), "r"(a1), "r"(a2), "r"(a3), "r"(b0), "r"(b1))

#define LDSM4(r0, r1, r2, r3, addr) \
    asm volatile("ldmatrix.sync.aligned.m8n8.x4.shared.b16 {%0,%1,%2,%3}, [%4];" \
                 : "=r"(r0), "=r"(r1), "=r"(r2), "=r"(r3) : "r"(addr))

// ---------------------------------------------------------------------------
// bf16x3 tensor-core GEMM body: C[M,N] = A[M,K] * W[N,K]^T (fp32-accurate).
// CTA tile 128(M) x 256(N), k-block 32, 512 threads (16 warps, 2 M x 8 N),
// warp tile 64x32. hi/lo bf16 split at smem-fill; D += Ah*Bh + Ah*Bl + Al*Bh.
// Register-prefetch double buffer; ldmatrix.x4 fragment loads.
// smem per stage: AHI[128][20] ALO[128][20] BHI[256][20] BLO[256][20]
//  = 15360 words; 2 stages = 120KB -> 1 CTA/SM, 4 warps/SMSP.
// ---------------------------------------------------------------------------
#define RS_    20
#define A2HI   0
#define A2LO   2560
#define B2HI   5120
#define B2LO   10240
#define STG2   15360
#define GEMM_SMEM (2 * STG2 * 4)
#define GEMM_THREADS 512

__device__ __forceinline__ void gemm_bf16x3_body(
    unsigned* smw,
    const float* __restrict__ A, const float* __restrict__ W,
    float* __restrict__ C, int Nn, int Kn, int m0, int n0,
    int do_rope, const float* __restrict__ freqs)
{
    const unsigned smb = (unsigned)__cvta_generic_to_shared(smw);
    const int tid  = threadIdx.x;
    const int lane = tid & 31;
    const int warp = tid >> 5;           // 0..15
    const int warpM = (warp >> 3) * 64;  // 0 or 64
    const int warpN = (warp & 7) * 32;   // 0,32,...,224
    const int r = lane >> 2;             // 0..7
    const int c = lane & 3;              // 0..3
    const int grp = lane >> 3;           // ldmatrix matrix selector
    const int lr  = lane & 7;            // row within 8

    const int lrow = tid >> 3;           // 0..63
    const int lg   = tid & 7;            // k float4 group

    float acc[4][4][4];
#pragma unroll
    for (int i = 0; i < 4; ++i)
#pragma unroll
        for (int j = 0; j < 4; ++j)
#pragma unroll
            for (int t = 0; t < 4; ++t) acc[i][j][t] = 0.f;

    const int NT = Kn >> 5;

    float4 pa[2], pb[4];

    auto issue_loads = [&](int it) {
        size_t k0 = (size_t)it * 32 + lg * 4;
#pragma unroll
        for (int i = 0; i < 2; ++i) {
            int rr = lrow + i * 64;
            pa[i] = *(const float4*)&A[(size_t)(m0 + rr) * Kn + k0];
        }
#pragma unroll
        for (int i = 0; i < 4; ++i) {
            int rr = lrow + i * 64;
            pb[i] = *(const float4*)&W[(size_t)(n0 + rr) * Kn + k0];
        }
    };

    auto store_tile = [&](int p) {
        unsigned* base = smw + p * STG2;
#pragma unroll
        for (int i = 0; i < 2; ++i) {
            int rr = lrow + i * 64;
            int w = rr * RS_ + lg * 2;
            unsigned h0 = pk2(pa[i].x, pa[i].y), h1 = pk2(pa[i].z, pa[i].w);
            *(uint2*)&base[A2HI + w] = make_uint2(h0, h1);
            *(uint2*)&base[A2LO + w] = make_uint2(
                pk2(pa[i].x - blo(h0), pa[i].y - bhi(h0)),
                pk2(pa[i].z - blo(h1), pa[i].w - bhi(h1)));
        }
#pragma unroll
        for (int i = 0; i < 4; ++i) {
            int rr = lrow + i * 64;
            int w = rr * RS_ + lg * 2;
            unsigned g0 = pk2(pb[i].x, pb[i].y), g1 = pk2(pb[i].z, pb[i].w);
            *(uint2*)&base[B2HI + w] = make_uint2(g0, g1);
            *(uint2*)&base[B2LO + w] = make_uint2(
                pk2(pb[i].x - blo(g0), pb[i].y - bhi(g0)),
                pk2(pb[i].z - blo(g1), pb[i].w - bhi(g1)));
        }
    };

    issue_loads(0);
    store_tile(0);
    __syncthreads();

    for (int it = 0; it < NT; ++it) {
        if (it + 1 < NT) issue_loads(it + 1);

        const unsigned sbase = smb + (unsigned)((it & 1) * STG2 * 4);
#pragma unroll
        for (int kk = 0; kk < 2; ++kk) {
            // B fragments: 2 bp groups (16 cols each) x (hi, lo)
            unsigned bh_[2][4], bl_[2][4];
#pragma unroll
            for (int bp = 0; bp < 2; ++bp) {
                unsigned baddr = sbase + B2HI * 4u +
                    (unsigned)(((warpN + bp * 16 + (grp >> 1) * 8 + lr) * RS_ + kk * 8) * 4 + (grp & 1) * 16);
                LDSM4(bh_[bp][0], bh_[bp][1], bh_[bp][2], bh_[bp][3], baddr);
                LDSM4(bl_[bp][0], bl_[bp][1], bl_[bp][2], bl_[bp][3], baddr + (B2LO - B2HI) * 4u);
            }
#pragma unroll
            for (int am = 0; am < 4; ++am) {
                unsigned aaddr = sbase +
                    (unsigned)(((warpM + am * 16 + (grp & 1) * 8 + lr) * RS_ + kk * 8) * 4 + (grp >> 1) * 16);
                unsigned ah0, ah1, ah2, ah3, al0, al1, al2, al3;
                LDSM4(ah0, ah1, ah2, ah3, aaddr);
                LDSM4(al0, al1, al2, al3, aaddr + A2LO * 4u);
#pragma unroll
                for (int bn = 0; bn < 4; ++bn) {
                    const int bp = bn >> 1, off = (bn & 1) * 2;
                    MMA_BF16(acc[am][bn], ah0, ah1, ah2, ah3, bh_[bp][off], bh_[bp][off + 1]);
                    MMA_BF16(acc[am][bn], ah0, ah1, ah2, ah3, bl_[bp][off], bl_[bp][off + 1]);
                    MMA_BF16(acc[am][bn], al0, al1, al2, al3, bh_[bp][off], bh_[bp][off + 1]);
                }
            }
        }

        if (it + 1 < NT) store_tile((it + 1) & 1);
        __syncthreads();
    }

    // epilogue (optionally fused RoPE)
#pragma unroll
    for (int am = 0; am < 4; ++am) {
        int m1 = m0 + warpM + am * 16 + r;
#pragma unroll
        for (int bn = 0; bn < 4; ++bn) {
            int n1 = n0 + warpN + bn * 8 + 2 * c;
            float2 v0 = make_float2(acc[am][bn][0], acc[am][bn][1]);
            float2 v1 = make_float2(acc[am][bn][2], acc[am][bn][3]);
            if (do_rope) {
                int j = (n1 & (HD_ - 1)) >> 1;
                int s0 = m1 & (S_ - 1);
                int s1 = (m1 + 8) & (S_ - 1);
                float2 cs0 = *(const float2*)&freqs[((size_t)s0 * 64 + j) * 2];
                float2 cs1 = *(const float2*)&freqs[((size_t)s1 * 64 + j) * 2];
                v0 = make_float2(v0.x * cs0.x - v0.y * cs0.y,
                                 v0.x * cs0.y + v0.y * cs0.x);
                v1 = make_float2(v1.x * cs1.x - v1.y * cs1.y,
                                 v1.x * cs1.y + v1.y * cs1.x);
            }
            *(float2*)&C[(size_t)m1 * Nn + n1] = v0;
            *(float2*)&C[(size_t)(m1 + 8) * Nn + n1] = v1;
        }
    }
}

// Generic GEMM (used for the output projection)
__global__ __launch_bounds__(GEMM_THREADS, 1) void gemm_bf16x3_kernel(
    const float* __restrict__ A, const float* __restrict__ W,
    float* __restrict__ C, int Nn, int Kn,
    int do_rope, const float* __restrict__ freqs)
{
    extern __shared__ unsigned smw[];
    gemm_bf16x3_body(smw, A, W, C, Nn, Kn,
                     blockIdx.y * 128, blockIdx.x * 256, do_rope, freqs);
}

// Fused QKV GEMM: one launch covers wq (8 n-tiles of 256), wk (2), wv (2).
__global__ __launch_bounds__(GEMM_THREADS, 1) void gemm_qkv_fused_kernel(
    const float* __restrict__ X,
    const float* __restrict__ WQ, const float* __restrict__ WK,
    const float* __restrict__ WV,
    float* __restrict__ Qo, float* __restrict__ Ko, float* __restrict__ Vo,
    const float* __restrict__ freqs)
{
    extern __shared__ unsigned smw[];
    const int bx = blockIdx.x;
    const float* W;
    float* C;
    int Nn, n0, rope;
    if (bx < 8)       { W = WQ; C = Qo; Nn = QD_; n0 = bx * 256;        rope = 1; }
    else if (bx < 10) { W = WK; C = Ko; Nn = KD_; n0 = (bx - 8) * 256;  rope = 1; }
    else              { W = WV; C = Vo; Nn = KD_; n0 = (bx - 10) * 256; rope = 0; }
    gemm_bf16x3_body(smw, X, W, C, Nn, DIM_, blockIdx.y * 128, n0, rope, freqs);
}

// ---------------------------------------------------------------------------
// Flash attention, GQA-packed bf16x3 (causal). One block = one kv-head x a
// 32-position q-window, with all G_=4 sharing q-heads packed as 128 virtual
// q-rows (head*32 + pos). K/V tiles loaded+converted ONCE for 4 heads.
// ---------------------------------------------------------------------------
#define QHI_OFF 0
#define QLO_OFF 8704
#define KHI_OFF 17408
#define KLO_OFF 21760
#define VHI_OFF 26112
#define VLO_OFF 30464
#define FLASH_SMEM_WORDS 34816

__global__ __launch_bounds__(256, 1) void flash_bf16_kernel(
    const float* __restrict__ Q, const float* __restrict__ K,
    const float* __restrict__ V, float* __restrict__ O)
{
    extern __shared__ unsigned smw[];
    unsigned* QHI = smw + QHI_OFF;
    unsigned* QLO = smw + QLO_OFF;
    unsigned* KHI = smw + KHI_OFF;
    unsigned* KLO = smw + KLO_OFF;
    unsigned* VHI = smw + VHI_OFF;
    unsigned* VLO = smw + VLO_OFF;
    const unsigned smb = (unsigned)__cvta_generic_to_shared(smw);

    const int bkv = blockIdx.x;                // 0..7
    const int ib  = (int)gridDim.y - 1 - (int)blockIdx.y;  // 0..63, heavy first
    const int b   = bkv / KVH_;
    const int kv  = bkv % KVH_;

    const float* Kg = K + (size_t)b * S_ * KD_ + (size_t)kv * HD_;
    const float* Vg = V + (size_t)b * S_ * KD_ + (size_t)kv * HD_;

    const int tid  = threadIdx.x;
    const int lane = tid & 31;
    const int warp = tid >> 5;
    const int r = lane >> 2;      // 0..7
    const int c = lane & 3;       // 0..3
    const int grp = lane >> 3;    // ldmatrix selector
    const int lr  = lane & 7;
    const float scale = 0.08838834764831845f;

    // ---- load + convert Q (4 heads x 32 pos = 128 virtual rows x 128) ----
    for (int i = tid; i < 128 * 32; i += 256) {
        int vr  = i >> 5;
        int hd4 = (i & 31) * 4;
        int hh  = vr >> 5;
        int sp  = vr & 31;
        float4 f = *(const float4*)&Q[(size_t)(b * S_ + ib * 32 + sp) * QD_ +
                                      (size_t)(kv * G_ + hh) * HD_ + hd4];
        unsigned h0 = pk2(f.x, f.y), h1 = pk2(f.z, f.w);
        unsigned l0 = pk2(f.x - blo(h0), f.y - bhi(h0));
        unsigned l1 = pk2(f.z - blo(h1), f.w - bhi(h1));
        int w = vr * 68 + (hd4 >> 1);
        QHI[w] = h0; QHI[w + 1] = h1;
        QLO[w] = l0; QLO[w + 1] = l1;
    }

    float m0 = -1e30f, m1 = -1e30f, l0s = 0.f, l1s = 0.f;
    float acc[16][4];
#pragma unroll
    for (int t = 0; t < 16; ++t)
#pragma unroll
        for (int e = 0; e < 4; ++e) acc[t][e] = 0.f;

    const int hw  = kv * G_ + (warp >> 1);            // this warp's q-head
    const int qr0 = ib * 32 + (warp & 1) * 16 + r;    // seq row of c0,c1
    const int qr1 = qr0 + 8;
    const int jmax = ib >> 1;

    for (int j = 0; j <= jmax; ++j) {
        __syncthreads();
        for (int i = tid; i < 64 * 32; i += 256) {
            int row = i >> 5;
            int hd4 = (i & 31) * 4;
            int w = row * 68 + (hd4 >> 1);
            float4 f = *(const float4*)&Kg[(size_t)(j * 64 + row) * KD_ + hd4];
            unsigned h0 = pk2(f.x, f.y), h1 = pk2(f.z, f.w);
            KHI[w] = h0; KHI[w + 1] = h1;
            KLO[w]     = pk2(f.x - blo(h0), f.y - bhi(h0));
            KLO[w + 1] = pk2(f.z - blo(h1), f.w - bhi(h1));
            float4 g = *(const float4*)&Vg[(size_t)(j * 64 + row) * KD_ + hd4];
            unsigned v0 = pk2(g.x, g.y), v1 = pk2(g.z, g.w);
            VHI[w] = v0; VHI[w + 1] = v1;
            VLO[w]     = pk2(g.x - blo(v0), g.y - bhi(v0));
            VLO[w + 1] = pk2(g.z - blo(v1), g.w - bhi(v1));
        }
        __syncthreads();

        // ---- QK^T (ldmatrix fragments) ----
        float s[8][4];
#pragma unroll
        for (int bn = 0; bn < 8; ++bn)
#pragma unroll
            for (int e = 0; e < 4; ++e) s[bn][e] = 0.f;

#pragma unroll
        for (int kk = 0; kk < 8; ++kk) {
            unsigned qaddr = smb +
                (unsigned)(((warp * 16 + (grp & 1) * 8 + lr) * 68 + kk * 8) * 4 + (grp >> 1) * 16);
            unsigned ah0, ah1, ah2, ah3, al0, al1, al2, al3;
            LDSM4(ah0, ah1, ah2, ah3, qaddr);
            LDSM4(al0, al1, al2, al3, qaddr + QLO_OFF * 4u);
#pragma unroll
            for (int bp = 0; bp < 4; ++bp) {
                unsigned kaddr = smb + KHI_OFF * 4u +
                    (unsigned)(((bp * 16 + (grp >> 1) * 8 + lr) * 68 + kk * 8) * 4 + (grp & 1) * 16);
                unsigned kh[4], kl[4];
                LDSM4(kh[0], kh[1], kh[2], kh[3], kaddr);
                LDSM4(kl[0], kl[1], kl[2], kl[3], kaddr + (KLO_OFF - KHI_OFF) * 4u);
                MMA_BF16(s[2 * bp],     ah0, ah1, ah2, ah3, kh[0], kh[1]);
                MMA_BF16(s[2 * bp],     ah0, ah1, ah2, ah3, kl[0], kl[1]);
                MMA_BF16(s[2 * bp],     al0, al1, al2, al3, kh[0], kh[1]);
                MMA_BF16(s[2 * bp + 1], ah0, ah1, ah2, ah3, kh[2], kh[3]);
                MMA_BF16(s[2 * bp + 1], ah0, ah1, ah2, ah3, kl[2], kl[3]);
                MMA_BF16(s[2 * bp + 1], al0, al1, al2, al3, kh[2], kh[3]);
            }
        }

        // ---- scale, mask, online softmax ----
        const bool need_mask = (j == jmax);
        float vmax0 = -1e30f, vmax1 = -1e30f;
#pragma unroll
        for (int bn = 0; bn < 8; ++bn) {
#pragma unroll
            for (int e = 0; e < 2; ++e) {
                int col = j * 64 + bn * 8 + 2 * c + e;
                float v0 = s[bn][e] * scale;
                if (need_mask && col > qr0) v0 = -1e30f;
                s[bn][e] = v0;
                vmax0 = fmaxf(vmax0, v0);
                float v1 = s[bn][2 + e] * scale;
                if (need_mask && col > qr1) v1 = -1e30f;
                s[bn][2 + e] = v1;
                vmax1 = fmaxf(vmax1, v1);
            }
        }
        vmax0 = fmaxf(vmax0, __shfl_xor_sync(0xffffffffu, vmax0, 1));
        vmax0 = fmaxf(vmax0, __shfl_xor_sync(0xffffffffu, vmax0, 2));
        vmax1 = fmaxf(vmax1, __shfl_xor_sync(0xffffffffu, vmax1, 1));
        vmax1 = fmaxf(vmax1, __shfl_xor_sync(0xffffffffu, vmax1, 2));

        float mn0 = fmaxf(m0, vmax0), mn1 = fmaxf(m1, vmax1);
        float alpha0 = __expf(m0 - mn0), alpha1 = __expf(m1 - mn1);
        m0 = mn0; m1 = mn1;

        float rs0 = 0.f, rs1 = 0.f;
#pragma unroll
        for (int bn = 0; bn < 8; ++bn) {
#pragma unroll
            for (int e = 0; e < 2; ++e) {
                float p0 = __expf(s[bn][e] - mn0);
                s[bn][e] = p0; rs0 += p0;
                float p1 = __expf(s[bn][2 + e] - mn1);
                s[bn][2 + e] = p1; rs1 += p1;
            }
        }
        rs0 += __shfl_xor_sync(0xffffffffu, rs0, 1);
        rs0 += __shfl_xor_sync(0xffffffffu, rs0, 2);
        rs1 += __shfl_xor_sync(0xffffffffu, rs1, 1);
        rs1 += __shfl_xor_sync(0xffffffffu, rs1, 2);
        l0s = l0s * alpha0 + rs0;
        l1s = l1s * alpha1 + rs1;

#pragma unroll
        for (int t = 0; t < 16; ++t) {
            acc[t][0] *= alpha0; acc[t][1] *= alpha0;
            acc[t][2] *= alpha1; acc[t][3] *= alpha1;
        }

        // ---- PV ----
#pragma unroll
        for (int kk = 0; kk < 4; ++kk) {
            unsigned ph0 = pk2(s[2 * kk][0], s[2 * kk][1]);
            unsigned ph1 = pk2(s[2 * kk][2], s[2 * kk][3]);
            unsigned ph2 = pk2(s[2 * kk + 1][0], s[2 * kk + 1][1]);
            unsigned ph3 = pk2(s[2 * kk + 1][2], s[2 * kk + 1][3]);
            unsigned pl0 = pk2(s[2 * kk][0] - blo(ph0), s[2 * kk][1] - bhi(ph0));
            unsigned pl1 = pk2(s[2 * kk][2] - blo(ph1), s[2 * kk][3] - bhi(ph1));
            unsigned pl2 = pk2(s[2 * kk + 1][0] - blo(ph2), s[2 * kk + 1][1] - bhi(ph2));
            unsigned pl3 = pk2(s[2 * kk + 1][2] - blo(ph3), s[2 * kk + 1][3] - bhi(ph3));

            int sel = lane >> 3;
            int lrw = lane & 7;
            int vrow = kk * 16 + (sel & 1) * 8 + lrw;
            int coff = (sel >> 1) * 8;

#pragma unroll
            for (int t = 0; t < 16; t += 2) {
                unsigned addr_h = smb + VHI_OFF * 4u + (unsigned)(vrow * 272 + (t * 8 + coff) * 2);
                unsigned addr_l = smb + VLO_OFF * 4u + (unsigned)(vrow * 272 + (t * 8 + coff) * 2);
                unsigned vh0, vh1, vh2, vh3, vl0, vl1, vl2, vl3;
                asm volatile("ldmatrix.sync.aligned.m8n8.x4.trans.shared.b16 {%0,%1,%2,%3}, [%4];"
                             : "=r"(vh0), "=r"(vh1), "=r"(vh2), "=r"(vh3) : "r"(addr_h));
                asm volatile("ldmatrix.sync.aligned.m8n8.x4.trans.shared.b16 {%0,%1,%2,%3}, [%4];"
                             : "=r"(vl0), "=r"(vl1), "=r"(vl2), "=r"(vl3) : "r"(addr_l));
                MMA_BF16(acc[t],     ph0, ph1, ph2, ph3, vh0, vh1);
                MMA_BF16(acc[t],     ph0, ph1, ph2, ph3, vl0, vl1);
                MMA_BF16(acc[t],     pl0, pl1, pl2, pl3, vh0, vh1);
                MMA_BF16(acc[t + 1], ph0, ph1, ph2, ph3, vh2, vh3);
                MMA_BF16(acc[t + 1], ph0, ph1, ph2, ph3, vl2, vl3);
                MMA_BF16(acc[t + 1], pl0, pl1, pl2, pl3, vh2, vh3);
            }
        }
    }

    // ---- epilogue: write attn[b, qr, hw, :] ----
    float inv0 = 1.f / l0s, inv1 = 1.f / l1s;
#pragma unroll
    for (int t = 0; t < 16; ++t) {
        int col = t * 8 + 2 * c;
        float* d0 = O + (size_t)(b * S_ + qr0) * QD_ + (size_t)hw * HD_ + col;
        float* d1 = O + (size_t)(b * S_ + qr1) * QD_ + (size_t)hw * HD_ + col;
        *(float2*)d0 = make_float2(acc[t][0] * inv0, acc[t][1] * inv0);
        *(float2*)d1 = make_float2(acc[t][2] * inv1, acc[t][3] * inv1);
    }
}

// ---------------------------------------------------------------------------
extern "C" void kernel_launch(void* const* d_in, const int* in_sizes, int n_in,
                              void* d_out, int out_size)
{
    const float* x     = (const float*)d_in[0];
    const float* freqs = (const float*)d_in[1];
    const float* wq    = (const float*)d_in[2];
    const float* wk    = (const float*)d_in[3];
    const float* wv    = (const float*)d_in[4];
    const float* wo    = (const float*)d_in[5];
    float* out = (float*)d_out;

    float *q, *k, *v, *attn;
    cudaGetSymbolAddress((void**)&q,    g_q);
    cudaGetSymbolAddress((void**)&k,    g_k);
    cudaGetSymbolAddress((void**)&v,    g_v);
    cudaGetSymbolAddress((void**)&attn, g_attn);

    static int attr_set = 0;
    const int flash_smem = FLASH_SMEM_WORDS * 4;  // 139264
    if (!attr_set) {
        cudaFuncSetAttribute(gemm_bf16x3_kernel,
                             cudaFuncAttributeMaxDynamicSharedMemorySize, GEMM_SMEM);
        cudaFuncSetAttribute(gemm_qkv_fused_kernel,
                             cudaFuncAttributeMaxDynamicSharedMemorySize, GEMM_SMEM);
        cudaFuncSetAttribute(flash_bf16_kernel,
                             cudaFuncAttributeMaxDynamicSharedMemorySize, flash_smem);
        attr_set = 1;
    }

    // Fused QKV projection: 12x32 = 384 blocks (8 Q + 2 K + 2 V n-tiles of 256)
    gemm_qkv_fused_kernel<<<dim3(12, M_ / 128), GEMM_THREADS, GEMM_SMEM>>>(
        x, wq, wk, wv, q, k, v, freqs);

    // Flash attention (GQA-packed: one block = kv-head x 32-pos window x 4 heads)
    flash_bf16_kernel<<<dim3(B_ * KVH_, S_ / 32), 256, flash_smem>>>(q, k, v, attn);

    // Output projection (bf16x3 tensor-core)
    gemm_bf16x3_kernel<<<dim3(DIM_ / 256, M_ / 128), GEMM_THREADS, GEMM_SMEM>>>(
        attn, wo, out, DIM_, QD_, 0, freqs);
}